// round 17
// baseline (speedup 1.0000x reference)
#include <cuda_runtime.h>
#include <cstdint>

#define B_SZ 256
#define C_SZ 3
#define H_SZ 224
#define W_SZ 224
#define P_SZ 1024
#define E_SZ 384

// R16 structure (best: 87.9us) + cross-round gather pipelining:
// block (96,4); each CTA handles 128 p's (4 rounds of 32 p's) for one batch.
// Round t+1's gathers are issued BEFORE round t's store loop, so stores+FMAs
// cover the gather DRAM latency — only round 0's latency is exposed.
__global__ __launch_bounds__(384) void patch_embed_kernel(
    const float* __restrict__ x,      // (B, C, H, W)
    const int*   __restrict__ curve,  // (P, 2): [:,0]=x-coord, [:,1]=y-coord
    const float* __restrict__ Wm,     // (E, C) row-major
    const float* __restrict__ bias,   // (E,)
    float* __restrict__ out)          // (B, 1, P, E)
{
    __shared__ float sW[E_SZ * C_SZ];
    __shared__ float sB[E_SZ];

    const int tid = threadIdx.y * 96 + threadIdx.x;   // 0..383
    sW[tid]        = __ldg(&Wm[tid]);
    sW[tid + 384]  = __ldg(&Wm[tid + 384]);
    sW[tid + 768]  = __ldg(&Wm[tid + 768]);
    sB[tid]        = __ldg(&bias[tid]);
    __syncthreads();

    const int e0 = threadIdx.x * 4;
    float4 w0, w1, w2, bb;
    w0.x = sW[(e0+0)*3+0]; w0.y = sW[(e0+1)*3+0]; w0.z = sW[(e0+2)*3+0]; w0.w = sW[(e0+3)*3+0];
    w1.x = sW[(e0+0)*3+1]; w1.y = sW[(e0+1)*3+1]; w1.z = sW[(e0+2)*3+1]; w1.w = sW[(e0+3)*3+1];
    w2.x = sW[(e0+0)*3+2]; w2.y = sW[(e0+1)*3+2]; w2.z = sW[(e0+2)*3+2]; w2.w = sW[(e0+3)*3+2];
    bb.x = sB[e0+0]; bb.y = sB[e0+1]; bb.z = sB[e0+2]; bb.w = sB[e0+3];

    const int b = blockIdx.y;
    const float* xb = x + (size_t)b * (C_SZ * H_SZ * W_SZ);
    float* outb = out + (size_t)b * (P_SZ * E_SZ);

    const int2* __restrict__ cv2 = (const int2*)curve;
    const int ptile0 = blockIdx.x * 128 + threadIdx.y;

    // Double-buffered gather registers.
    float ga0[8], ga1[8], ga2[8];   // current round
    float gb0[8], gb1[8], gb2[8];   // next round (prefetch)

    // Prologue: gathers for round 0.
    #pragma unroll
    for (int i = 0; i < 8; i++) {
        const int2 cv = __ldg(&cv2[ptile0 + i * 4]);
        const int off = cv.y * W_SZ + cv.x;
        ga0[i] = __ldg(xb + off);
        ga1[i] = __ldg(xb + H_SZ * W_SZ + off);
        ga2[i] = __ldg(xb + 2 * H_SZ * W_SZ + off);
    }

    #pragma unroll
    for (int t = 0; t < 4; t++) {
        // Prefetch round t+1's gathers before storing round t.
        if (t < 3) {
            const int pnext = ptile0 + (t + 1) * 32;
            #pragma unroll
            for (int i = 0; i < 8; i++) {
                const int2 cv = __ldg(&cv2[pnext + i * 4]);
                const int off = cv.y * W_SZ + cv.x;
                gb0[i] = __ldg(xb + off);
                gb1[i] = __ldg(xb + H_SZ * W_SZ + off);
                gb2[i] = __ldg(xb + 2 * H_SZ * W_SZ + off);
            }
        }

        // FMA + coalesced float4 stores for round t (covers prefetch latency).
        const int pbase = ptile0 + t * 32;
        #pragma unroll
        for (int i = 0; i < 8; i++) {
            const int p = pbase + i * 4;
            float4 r;
            r.x = fmaf(ga0[i], w0.x, fmaf(ga1[i], w1.x, fmaf(ga2[i], w2.x, bb.x)));
            r.y = fmaf(ga0[i], w0.y, fmaf(ga1[i], w1.y, fmaf(ga2[i], w2.y, bb.y)));
            r.z = fmaf(ga0[i], w0.z, fmaf(ga1[i], w1.z, fmaf(ga2[i], w2.z, bb.z)));
            r.w = fmaf(ga0[i], w0.w, fmaf(ga1[i], w1.w, fmaf(ga2[i], w2.w, bb.w)));
            float4* dst = (float4*)(outb + (size_t)p * E_SZ) + threadIdx.x;
            *dst = r;
        }

        // Rotate buffers.
        #pragma unroll
        for (int i = 0; i < 8; i++) {
            ga0[i] = gb0[i]; ga1[i] = gb1[i]; ga2[i] = gb2[i];
        }
    }
}

extern "C" void kernel_launch(void* const* d_in, const int* in_sizes, int n_in,
                              void* d_out, int out_size) {
    const float* x     = (const float*)d_in[0];
    const int*   curve = (const int*)d_in[1];
    const float* Wm    = (const float*)d_in[2];
    const float* bias  = (const float*)d_in[3];
    float* out = (float*)d_out;

    dim3 block(96, 4);
    dim3 grid(P_SZ / 128, B_SZ);   // 8 x 256 = 2048 CTAs
    patch_embed_kernel<<<grid, block>>>(x, curve, Wm, bias, out);
}